// round 6
// baseline (speedup 1.0000x reference)
#include <cuda_runtime.h>
#include <cuda_bf16.h>
#include <cstdint>

// Problem constants
#define TT      524288
#define INLEN   64
#define NMEM    64
#define HID     128       // 2*NMEM
#define OUTLEN  32
#define CHUNK   128
#define NCH     (TT / CHUNK)   // 4096

// Scratch (device globals — allocation-free rule)
__device__ float g_cA[NMEM * NCH];      // per-chunk composed A, CHANNEL-MAJOR [ch][c]
__device__ float g_cB[NMEM * NCH];      // per-chunk composed B, CHANNEL-MAJOR [ch][c]
__device__ float g_pB[NCH * NMEM];      // exclusive-prefix B = z at chunk start [c][ch]

// ===================== helpers =====================
__device__ __forceinline__ uint32_t smem_u32(const void* p) {
    uint32_t a;
    asm("{ .reg .u64 t; cvta.to.shared.u64 t, %1; cvt.u32.u64 %0, t; }" : "=r"(a) : "l"(p));
    return a;
}
__device__ __forceinline__ float sigmoidf_(float x) {
    return __fdividef(1.0f, 1.0f + __expf(-x));
}
__device__ __forceinline__ unsigned long long pk2(float lo, float hi) {
    unsigned long long r;
    asm("mov.b64 %0, {%1, %2};" : "=l"(r) : "f"(lo), "f"(hi));
    return r;
}
__device__ __forceinline__ void fma2(unsigned long long& d, unsigned long long a,
                                     unsigned long long b) {
    asm("fma.rn.f32x2 %0, %1, %2, %3;" : "=l"(d) : "l"(a), "l"(b), "l"(d));
}
__device__ __forceinline__ float2 unpk2(unsigned long long v) {
    float2 r;
    asm("mov.b64 {%0, %1}, %2;" : "=f"(r.x), "=f"(r.y) : "l"(v));
    return r;
}
// base-target tensor path (valid on plain sm_103)
__device__ __forceinline__ void ldsm_x4(uint32_t* r, uint32_t a) {
    asm volatile("ldmatrix.sync.aligned.m8n8.x4.shared.b16 {%0,%1,%2,%3}, [%4];"
                 : "=r"(r[0]), "=r"(r[1]), "=r"(r[2]), "=r"(r[3]) : "r"(a));
}
__device__ __forceinline__ void mma16816(float* c, const uint32_t* a,
                                         uint32_t b0, uint32_t b1) {
    asm volatile("mma.sync.aligned.m16n8k16.row.col.f32.bf16.bf16.f32 "
                 "{%0,%1,%2,%3}, {%4,%5,%6,%7}, {%8,%9}, {%0,%1,%2,%3};"
                 : "+f"(c[0]), "+f"(c[1]), "+f"(c[2]), "+f"(c[3])
                 : "r"(a[0]), "r"(a[1]), "r"(a[2]), "r"(a[3]), "r"(b0), "r"(b1));
}
// bf16 hi/lo split of two floats, packed as bf16x2 words
__device__ __forceinline__ void bfsplit2(float x, float y, uint32_t& hi, uint32_t& lo) {
    __nv_bfloat16 hx = __float2bfloat16_rn(x);
    __nv_bfloat16 hy = __float2bfloat16_rn(y);
    __nv_bfloat16 lx = __float2bfloat16_rn(x - __bfloat162float(hx));
    __nv_bfloat16 ly = __float2bfloat16_rn(y - __bfloat162float(hy));
    hi = (uint32_t)__bfloat16_as_ushort(hx) | ((uint32_t)__bfloat16_as_ushort(hy) << 16);
    lo = (uint32_t)__bfloat16_as_ushort(lx) | ((uint32_t)__bfloat16_as_ushort(ly) << 16);
}

// SMEM layout (byte offsets from 1024-aligned base). Tile rows padded to
// 72 bf16 = 144 B so ldmatrix row addresses hit distinct banks.
#define TSTRIDE 144
#define OFF_AH  0            // x hi  [128 m][72 k] bf16 : 18432 B
#define OFF_AL  18432        // x lo
#define OFF_BH  36864        // W1^T hi [128 n][72 k] bf16
#define OFF_BL  55296        //           ... ends at 73728
#define OFF_HS  0            // f32 [128][132] = 67584 B, OVERLAYS tiles (post-MMA)
#define HS_ST   132
#define OFF_ZS  67584        // f32 [64][132] = 33792 B (phase3; after Hs)
#define OFF_W2  101376       // f32 [64][32]  = 8192 B  (phase3)
#define P1_DSMEM (73728 + 1024)
#define P3_DSMEM (109568 + 1024)

// =====================================================================
// GEMM1 via mma.sync bf16-split: writes Hs[row][col] = sigmoid(x@W1+B1).
// 512 threads = 16 warps: warp = (m-tile 0..7, n-half 0..1); each warp does
// 8 n-tiles x 4 k-steps x 3 passes = 96 HMMA. Ends with Hs valid + barrier.
// =====================================================================
__device__ __forceinline__ void gemm1_hs(
    const float* __restrict__ xblk, const float* __restrict__ W1,
    const float* __restrict__ B1,
    char* base_c, uint32_t base_u, float* b1s, int tid) {

    char* Ah = base_c + OFF_AH;
    char* Al = base_c + OFF_AL;
    char* Bh = base_c + OFF_BH;
    char* Bl = base_c + OFF_BL;

    // ---- A tiles: x chunk [128 m][64 k] f32 -> bf16 hi/lo ----
#pragma unroll
    for (int it = 0; it < 4; it++) {
        int i = it * 512 + tid;          // float4 idx: row = i>>4, kq = i&15
        int row = i >> 4, kq = i & 15;
        float4 v = ((const float4*)xblk)[i];
        uint2 ph, pl;
        bfsplit2(v.x, v.y, ph.x, pl.x);
        bfsplit2(v.z, v.w, ph.y, pl.y);
        uint32_t off = row * TSTRIDE + kq * 8;
        *(uint2*)(Ah + off) = ph;
        *(uint2*)(Al + off) = pl;
    }
    // ---- B tiles: W1[k][n] -> [n][k] bf16 hi/lo ----
#pragma unroll
    for (int it = 0; it < 16; it++) {
        int i = it * 512 + tid;          // k = i>>7, n = i&127 (coalesced read)
        int k = i >> 7, n = i & 127;
        float v = W1[i];
        __nv_bfloat16 h = __float2bfloat16_rn(v);
        __nv_bfloat16 l = __float2bfloat16_rn(v - __bfloat162float(h));
        uint32_t off = n * TSTRIDE + k * 2;
        *(__nv_bfloat16*)(Bh + off) = h;
        *(__nv_bfloat16*)(Bl + off) = l;
    }
    if (tid < HID) b1s[tid] = B1[tid];
    __syncthreads();

    const int wid  = tid >> 5, lane = tid & 31;
    const int mw   = wid & 7;      // m-tile: rows 16*mw..+15
    const int nh   = wid >> 3;     // n-half: n-tiles 8*nh..+7

    // ---- preload A fragments for 4 k-steps, hi+lo ----
    uint32_t AhF[4][4], AlF[4][4];
    {
        uint32_t arow  = mw * 16 + (lane & 15);
        uint32_t acol8 = (lane >> 4) << 3;     // 0 or 8
#pragma unroll
        for (int kk = 0; kk < 4; kk++) {
            uint32_t ad = base_u + OFF_AH + arow * TSTRIDE + (kk * 16 + acol8) * 2;
            ldsm_x4(AhF[kk], ad);
            ldsm_x4(AlF[kk], ad + (OFF_AL - OFF_AH));
        }
    }

    float acc[8][4];
#pragma unroll
    for (int j = 0; j < 8; j++)
#pragma unroll
        for (int q = 0; q < 4; q++) acc[j][q] = 0.0f;

    const uint32_t brow7 = lane & 7;
    const uint32_t bcol8 = (lane >> 3) << 3;   // 0,8,16,24 -> k offsets in 32-block
#pragma unroll
    for (int j = 0; j < 8; j++) {
        int jn = nh * 8 + j;                   // global n-tile
#pragma unroll
        for (int kk2 = 0; kk2 < 2; kk2++) {    // k 0-31, 32-63
            uint32_t bd = base_u + OFF_BH + (8 * jn + brow7) * TSTRIDE
                        + (kk2 * 32 + bcol8) * 2;
            uint32_t Bhf[4], Blf[4];
            ldsm_x4(Bhf, bd);
            ldsm_x4(Blf, bd + (OFF_BL - OFF_BH));
#pragma unroll
            for (int sh = 0; sh < 2; sh++) {
                int s = kk2 * 2 + sh;
                mma16816(acc[j], AhF[s], Bhf[sh * 2], Bhf[sh * 2 + 1]);  // xh*Wh
                mma16816(acc[j], AhF[s], Blf[sh * 2], Blf[sh * 2 + 1]);  // xh*Wl
                mma16816(acc[j], AlF[s], Bhf[sh * 2], Bhf[sh * 2 + 1]);  // xl*Wh
            }
        }
    }
    __syncthreads();   // all MMAs done -> bf16 tiles dead, Hs overlay safe

    // ---- epilogue: bias + sigmoid -> Hs ----
    float* Hs = (float*)(base_c + OFF_HS);
    {
        int r0 = mw * 16 + (lane >> 2);
        int c0 = (lane & 3) * 2;
#pragma unroll
        for (int j = 0; j < 8; j++) {
            int n = 8 * (nh * 8 + j) + c0;
            Hs[r0 * HS_ST + n]           = sigmoidf_(acc[j][0] + b1s[n]);
            Hs[r0 * HS_ST + n + 1]       = sigmoidf_(acc[j][1] + b1s[n + 1]);
            Hs[(r0 + 8) * HS_ST + n]     = sigmoidf_(acc[j][2] + b1s[n]);
            Hs[(r0 + 8) * HS_ST + n + 1] = sigmoidf_(acc[j][3] + b1s[n + 1]);
        }
    }
    __syncthreads();
}

// =====================================================================
// Phase 1: chunk aggregates only.
// =====================================================================
__global__ __launch_bounds__(512, 1) void phase1_kernel(
    const float* __restrict__ x, const float* __restrict__ W1,
    const float* __restrict__ B1) {
    extern __shared__ char dyn[];
    __shared__ float b1s[HID];
    __shared__ float QA[8 * NMEM], QB[8 * NMEM];

    const int tid = threadIdx.x;
    const int c   = blockIdx.x;
    uint32_t du = smem_u32(dyn);
    uint32_t bu = (du + 1023u) & ~1023u;
    char* base_c = dyn + (bu - du);
    float* Hs = (float*)(base_c + OFF_HS);

    gemm1_hs(x + (size_t)c * CHUNK * INLEN, W1, B1, base_c, bu, b1s, tid);

    // compose: 8 segments of 16 rows per channel
    const int ch = tid & 63, q = tid >> 6;
    {
        float A = 1.0f, Bv = 0.0f;
#pragma unroll
        for (int t = 0; t < 16; t++) {
            int row = q * 16 + t;
            float l = Hs[row * HS_ST + ch];
            float r = Hs[row * HS_ST + ch + 64];
            float a = l * r, b = 1.0f - l;
            Bv = a * Bv + b;
            A *= a;
        }
        QA[q * NMEM + ch] = A;
        QB[q * NMEM + ch] = Bv;
    }
    __syncthreads();
    if (tid < NMEM) {
        float A = 1.0f, Bv = 0.0f;
#pragma unroll
        for (int qq = 0; qq < 8; qq++) {
            float a = QA[qq * NMEM + tid], b = QB[qq * NMEM + tid];
            Bv = a * Bv + b;
            A *= a;
        }
        g_cA[tid * NCH + c] = A;    // channel-major for phase2
        g_cB[tid * NCH + c] = Bv;
    }
}

// =====================================================================
// Phase 2: hierarchical exclusive scan over 4096 chunk compositions.
// =====================================================================
__global__ __launch_bounds__(256) void phase2_kernel() {
    __shared__ float cAs[NCH], cBs[NCH];
    __shared__ float SA[256], SB[256];
    const int ch  = blockIdx.x;
    const int tid = threadIdx.x;

    for (int i = tid; i < NCH / 4; i += 256) {
        ((float4*)cAs)[i] = ((const float4*)(g_cA + (size_t)ch * NCH))[i];
        ((float4*)cBs)[i] = ((const float4*)(g_cB + (size_t)ch * NCH))[i];
    }
    __syncthreads();

    const int base = tid * 16;
    float A = 1.0f, Bv = 0.0f;
#pragma unroll
    for (int j = 0; j < 16; j++) {
        float a = cAs[base + j], b = cBs[base + j];
        Bv = a * Bv + b;
        A *= a;
    }
    SA[tid] = A; SB[tid] = Bv;
    __syncthreads();

#pragma unroll
    for (int s = 1; s < 256; s <<= 1) {
        float ta = SA[tid], tb = SB[tid];
        float pa = 1.0f, pb = 0.0f;
        if (tid >= s) { pa = SA[tid - s]; pb = SB[tid - s]; }
        __syncthreads();
        if (tid >= s) { SA[tid] = ta * pa; SB[tid] = ta * pb + tb; }
        __syncthreads();
    }

    float PB = (tid > 0) ? SB[tid - 1] : 0.0f;
#pragma unroll
    for (int j = 0; j < 16; j++) {
        g_pB[(size_t)(base + j) * NMEM + ch] = PB;
        PB = cAs[base + j] * PB + cBs[base + j];
    }
}

// =====================================================================
// Phase 3: recompute h via tensor GEMM1, in-chunk scan -> Zs, GEMM2.
// =====================================================================
__global__ __launch_bounds__(512, 1) void phase3_kernel(
    const float* __restrict__ x, const float* __restrict__ W1,
    const float* __restrict__ B1, const float* __restrict__ W2,
    const float* __restrict__ B2, float* __restrict__ out) {
    extern __shared__ char dyn[];
    __shared__ float b1s[HID];
    __shared__ float QA[8 * NMEM], QB[8 * NMEM];
    __shared__ float pBs[NMEM];

    const int tid = threadIdx.x;
    const int c   = blockIdx.x;
    uint32_t du = smem_u32(dyn);
    uint32_t bu = (du + 1023u) & ~1023u;
    char* base_c = dyn + (bu - du);
    float* Hs  = (float*)(base_c + OFF_HS);
    float* Zs  = (float*)(base_c + OFF_ZS);   // [64 ch][132 rows]
    float* W2s = (float*)(base_c + OFF_W2);   // [64][32]

    // prefetch (regions disjoint from bf16 tiles)
    ((float4*)W2s)[tid] = ((const float4*)W2)[tid];   // 512 float4 = 2048 f
    if (tid < NMEM) pBs[tid] = g_pB[(size_t)c * NMEM + tid];

    gemm1_hs(x + (size_t)c * CHUNK * INLEN, W1, B1, base_c, bu, b1s, tid);

    // pass 1: compose 16-row sub-segments
    const int ch = tid & 63, q = tid >> 6;
    {
        float A = 1.0f, Bv = 0.0f;
#pragma unroll
        for (int t = 0; t < 16; t++) {
            int row = q * 16 + t;
            float l = Hs[row * HS_ST + ch];
            float r = Hs[row * HS_ST + ch + 64];
            float a = l * r, b = 1.0f - l;
            Bv = a * Bv + b;
            A *= a;
        }
        QA[q * NMEM + ch] = A;
        QB[q * NMEM + ch] = Bv;
    }
    __syncthreads();
    // pass 2: replay, writing z transposed into Zs[ch][row]
    {
        float u = pBs[ch];
#pragma unroll
        for (int j = 0; j < 7; j++)
            if (j < q) u = QA[j * NMEM + ch] * u + QB[j * NMEM + ch];
#pragma unroll
        for (int t = 0; t < 16; t++) {
            int row = q * 16 + t;
            float l = Hs[row * HS_ST + ch];
            float r = Hs[row * HS_ST + ch + 64];
            Zs[ch * HS_ST + row] = u;
            u = (l * r) * u + (1.0f - l);
        }
    }
    __syncthreads();

    // GEMM2: out[128][32] = Zs^T @ W2s + B2. Tile 2 rows x 4 cols.
    const int colg = (tid & 7) * 4;    // 0..28
    const int rowg = (tid >> 3) * 2;   // 0..126
    unsigned long long a00 = 0ull, a01 = 0ull, a10 = 0ull, a11 = 0ull;

#pragma unroll 8
    for (int k = 0; k < 64; k++) {
        float4 w = *(const float4*)&W2s[k * 32 + colg];
        float z0 = Zs[k * HS_ST + rowg];
        float z1 = Zs[k * HS_ST + rowg + 1];
        unsigned long long w0 = pk2(w.x, w.y), w1 = pk2(w.z, w.w);
        unsigned long long zz0 = pk2(z0, z0), zz1 = pk2(z1, z1);
        fma2(a00, zz0, w0); fma2(a01, zz0, w1);
        fma2(a10, zz1, w0); fma2(a11, zz1, w1);
    }

    float b0 = B2[colg + 0], b1 = B2[colg + 1], b2 = B2[colg + 2], b3 = B2[colg + 3];
    {
        float2 lo = unpk2(a00), hi = unpk2(a01);
        float4 o; o.x = lo.x + b0; o.y = lo.y + b1; o.z = hi.x + b2; o.w = hi.y + b3;
        size_t row = (size_t)c * CHUNK + rowg;
        *(float4*)&out[row * OUTLEN + colg] = o;
    }
    {
        float2 lo = unpk2(a10), hi = unpk2(a11);
        float4 o; o.x = lo.x + b0; o.y = lo.y + b1; o.z = hi.x + b2; o.w = hi.y + b3;
        size_t row = (size_t)c * CHUNK + rowg + 1;
        *(float4*)&out[row * OUTLEN + colg] = o;
    }
}

// =====================================================================
extern "C" void kernel_launch(void* const* d_in, const int* in_sizes, int n_in,
                              void* d_out, int out_size) {
    const float* x  = (const float*)d_in[0];   // [T, 64]
    const float* W1 = (const float*)d_in[1];   // [64, 128]
    const float* B1 = (const float*)d_in[2];   // [1, 128]
    const float* W2 = (const float*)d_in[3];   // [64, 32]
    const float* B2 = (const float*)d_in[4];   // [1, 32]
    float* out = (float*)d_out;                // [T, 32]

    cudaFuncSetAttribute(phase1_kernel, cudaFuncAttributeMaxDynamicSharedMemorySize, P1_DSMEM);
    cudaFuncSetAttribute(phase3_kernel, cudaFuncAttributeMaxDynamicSharedMemorySize, P3_DSMEM);

    phase1_kernel<<<NCH, 512, P1_DSMEM>>>(x, W1, B1);
    phase2_kernel<<<64, 256>>>();
    phase3_kernel<<<NCH, 512, P3_DSMEM>>>(x, W1, B1, W2, B2, out);
}

// round 8
// speedup vs baseline: 2.0857x; 2.0857x over previous
#include <cuda_runtime.h>
#include <cuda_bf16.h>
#include <cstdint>

// Problem constants
#define TT      524288
#define INLEN   64
#define NMEM    64
#define HID     128       // 2*NMEM
#define OUTLEN  32
#define CHUNK   128
#define NCH     (TT / CHUNK)   // 4096

// Scratch (device globals — allocation-free rule)
__device__ float g_a[TT * NMEM];        // 134 MB
__device__ float g_b[TT * NMEM];        // 134 MB
__device__ float g_cA[NMEM * NCH];      // per-chunk composed A, CHANNEL-MAJOR [ch][c]
__device__ float g_cB[NMEM * NCH];      // per-chunk composed B, CHANNEL-MAJOR [ch][c]
__device__ float g_pB[NCH * NMEM];      // exclusive-prefix B = z at chunk start [c][ch]

// ===================== helpers =====================
__device__ __forceinline__ uint32_t smem_u32(const void* p) {
    uint32_t a;
    asm("{ .reg .u64 t; cvta.to.shared.u64 t, %1; cvt.u32.u64 %0, t; }" : "=r"(a) : "l"(p));
    return a;
}
__device__ __forceinline__ float sigmoidf_(float x) {
    return __fdividef(1.0f, 1.0f + __expf(-x));
}
// base-target tensor path (valid on plain sm_103)
__device__ __forceinline__ void ldsm_x4(uint32_t* r, uint32_t a) {
    asm volatile("ldmatrix.sync.aligned.m8n8.x4.shared.b16 {%0,%1,%2,%3}, [%4];"
                 : "=r"(r[0]), "=r"(r[1]), "=r"(r[2]), "=r"(r[3]) : "r"(a));
}
__device__ __forceinline__ void mma16816(float* c, const uint32_t* a,
                                         uint32_t b0, uint32_t b1) {
    asm volatile("mma.sync.aligned.m16n8k16.row.col.f32.bf16.bf16.f32 "
                 "{%0,%1,%2,%3}, {%4,%5,%6,%7}, {%8,%9}, {%0,%1,%2,%3};"
                 : "+f"(c[0]), "+f"(c[1]), "+f"(c[2]), "+f"(c[3])
                 : "r"(a[0]), "r"(a[1]), "r"(a[2]), "r"(a[3]), "r"(b0), "r"(b1));
}
// bf16 hi/lo split of two floats, packed as bf16x2 words
__device__ __forceinline__ void bfsplit2(float x, float y, uint32_t& hi, uint32_t& lo) {
    __nv_bfloat16 hx = __float2bfloat16_rn(x);
    __nv_bfloat16 hy = __float2bfloat16_rn(y);
    __nv_bfloat16 lx = __float2bfloat16_rn(x - __bfloat162float(hx));
    __nv_bfloat16 ly = __float2bfloat16_rn(y - __bfloat162float(hy));
    hi = (uint32_t)__bfloat16_as_ushort(hx) | ((uint32_t)__bfloat16_as_ushort(hy) << 16);
    lo = (uint32_t)__bfloat16_as_ushort(lx) | ((uint32_t)__bfloat16_as_ushort(ly) << 16);
}

// SMEM layout (byte offsets from 1024-aligned base). Tile rows padded to
// 72 bf16 = 144 B so ldmatrix row addresses hit distinct banks.
#define TSTRIDE 144
#define OFF_AH  0            // x hi  [128 m][72 k] bf16 : 18432 B
#define OFF_AL  18432        // x lo
#define OFF_BH  36864        // W1^T hi [128 n][72 k] bf16
#define OFF_BL  55296        //           ... ends at 73728
#define OFF_HS  0            // f32 [128][132] = 67584 B, OVERLAYS tiles (post-MMA)
#define HS_ST   132
#define P1_DSMEM (73728 + 1024)

// =====================================================================
// GEMM1 via mma.sync bf16-split: writes Hs[row][col] = sigmoid(x@W1+B1).
// 512 threads = 16 warps: warp = (m-tile 0..7, n-half 0..1); each warp does
// 8 n-tiles x 4 k-steps x 3 passes = 96 HMMA. Ends with Hs valid + barrier.
// =====================================================================
__device__ __forceinline__ void gemm1_hs(
    const float* __restrict__ xblk, const float* __restrict__ W1,
    const float* __restrict__ B1,
    char* base_c, uint32_t base_u, float* b1s, int tid) {

    char* Ah = base_c + OFF_AH;
    char* Al = base_c + OFF_AL;
    char* Bh = base_c + OFF_BH;
    char* Bl = base_c + OFF_BL;

    // ---- A tiles: x chunk [128 m][64 k] f32 -> bf16 hi/lo ----
#pragma unroll
    for (int it = 0; it < 4; it++) {
        int i = it * 512 + tid;          // float4 idx: row = i>>4, kq = i&15
        int row = i >> 4, kq = i & 15;
        float4 v = ((const float4*)xblk)[i];
        uint2 ph, pl;
        bfsplit2(v.x, v.y, ph.x, pl.x);
        bfsplit2(v.z, v.w, ph.y, pl.y);
        uint32_t off = row * TSTRIDE + kq * 8;
        *(uint2*)(Ah + off) = ph;
        *(uint2*)(Al + off) = pl;
    }
    // ---- B tiles: W1[k][n] -> [n][k] bf16 hi/lo ----
#pragma unroll
    for (int it = 0; it < 16; it++) {
        int i = it * 512 + tid;          // k = i>>7, n = i&127 (coalesced read)
        int k = i >> 7, n = i & 127;
        float v = W1[i];
        __nv_bfloat16 h = __float2bfloat16_rn(v);
        __nv_bfloat16 l = __float2bfloat16_rn(v - __bfloat162float(h));
        uint32_t off = n * TSTRIDE + k * 2;
        *(__nv_bfloat16*)(Bh + off) = h;
        *(__nv_bfloat16*)(Bl + off) = l;
    }
    if (tid < HID) b1s[tid] = B1[tid];
    __syncthreads();

    const int wid  = tid >> 5, lane = tid & 31;
    const int mw   = wid & 7;      // m-tile: rows 16*mw..+15
    const int nh   = wid >> 3;     // n-half: n-tiles 8*nh..+7

    // ---- preload A fragments for 4 k-steps, hi+lo ----
    uint32_t AhF[4][4], AlF[4][4];
    {
        uint32_t arow  = mw * 16 + (lane & 15);
        uint32_t acol8 = (lane >> 4) << 3;     // 0 or 8
#pragma unroll
        for (int kk = 0; kk < 4; kk++) {
            uint32_t ad = base_u + OFF_AH + arow * TSTRIDE + (kk * 16 + acol8) * 2;
            ldsm_x4(AhF[kk], ad);
            ldsm_x4(AlF[kk], ad + (OFF_AL - OFF_AH));
        }
    }

    float acc[8][4];
#pragma unroll
    for (int j = 0; j < 8; j++)
#pragma unroll
        for (int q = 0; q < 4; q++) acc[j][q] = 0.0f;

    const uint32_t brow7 = lane & 7;
    const uint32_t bcol8 = (lane >> 3) << 3;   // 0,8,16,24 -> k offsets in 32-block
#pragma unroll
    for (int j = 0; j < 8; j++) {
        int jn = nh * 8 + j;                   // global n-tile
#pragma unroll
        for (int kk2 = 0; kk2 < 2; kk2++) {    // k 0-31, 32-63
            uint32_t bd = base_u + OFF_BH + (8 * jn + brow7) * TSTRIDE
                        + (kk2 * 32 + bcol8) * 2;
            uint32_t Bhf[4], Blf[4];
            ldsm_x4(Bhf, bd);
            ldsm_x4(Blf, bd + (OFF_BL - OFF_BH));
#pragma unroll
            for (int sh = 0; sh < 2; sh++) {
                int s = kk2 * 2 + sh;
                mma16816(acc[j], AhF[s], Bhf[sh * 2], Bhf[sh * 2 + 1]);  // xh*Wh
                mma16816(acc[j], AhF[s], Blf[sh * 2], Blf[sh * 2 + 1]);  // xh*Wl
                mma16816(acc[j], AlF[s], Bhf[sh * 2], Bhf[sh * 2 + 1]);  // xl*Wh
            }
        }
    }
    __syncthreads();   // all MMAs done -> bf16 tiles dead, Hs overlay safe

    // ---- epilogue: bias + sigmoid -> Hs ----
    float* Hs = (float*)(base_c + OFF_HS);
    {
        int r0 = mw * 16 + (lane >> 2);
        int c0 = (lane & 3) * 2;
#pragma unroll
        for (int j = 0; j < 8; j++) {
            int n = 8 * (nh * 8 + j) + c0;
            Hs[r0 * HS_ST + n]           = sigmoidf_(acc[j][0] + b1s[n]);
            Hs[r0 * HS_ST + n + 1]       = sigmoidf_(acc[j][1] + b1s[n + 1]);
            Hs[(r0 + 8) * HS_ST + n]     = sigmoidf_(acc[j][2] + b1s[n]);
            Hs[(r0 + 8) * HS_ST + n + 1] = sigmoidf_(acc[j][3] + b1s[n + 1]);
        }
    }
    __syncthreads();
}

// =====================================================================
// Phase 1: tensor GEMM1 -> Hs; write a,b to gmem; chunk aggregates.
// =====================================================================
__global__ __launch_bounds__(512, 1) void phase1_kernel(
    const float* __restrict__ x, const float* __restrict__ W1,
    const float* __restrict__ B1) {
    extern __shared__ char dyn[];
    __shared__ float b1s[HID];
    __shared__ float QA[8 * NMEM], QB[8 * NMEM];

    const int tid = threadIdx.x;
    const int c   = blockIdx.x;
    uint32_t du = smem_u32(dyn);
    uint32_t bu = (du + 1023u) & ~1023u;
    char* base_c = dyn + (bu - du);
    float* Hs = (float*)(base_c + OFF_HS);

    gemm1_hs(x + (size_t)c * CHUNK * INLEN, W1, B1, base_c, bu, b1s, tid);

    // write a,b to gmem (coalesced): layout [T][64]
    const size_t gbase = (size_t)c * CHUNK * NMEM;
#pragma unroll 4
    for (int i = tid; i < CHUNK * NMEM; i += 512) {
        int t = i >> 6, ch = i & 63;
        float l = Hs[t * HS_ST + ch];
        float r = Hs[t * HS_ST + ch + 64];
        g_a[gbase + i] = l * r;
        g_b[gbase + i] = 1.0f - l;
    }

    // compose: 8 segments of 16 rows per channel
    const int ch = tid & 63, q = tid >> 6;
    {
        float A = 1.0f, Bv = 0.0f;
#pragma unroll
        for (int t = 0; t < 16; t++) {
            int row = q * 16 + t;
            float l = Hs[row * HS_ST + ch];
            float r = Hs[row * HS_ST + ch + 64];
            float a = l * r, b = 1.0f - l;
            Bv = a * Bv + b;
            A *= a;
        }
        QA[q * NMEM + ch] = A;
        QB[q * NMEM + ch] = Bv;
    }
    __syncthreads();
    if (tid < NMEM) {
        float A = 1.0f, Bv = 0.0f;
#pragma unroll
        for (int qq = 0; qq < 8; qq++) {
            float a = QA[qq * NMEM + tid], b = QB[qq * NMEM + tid];
            Bv = a * Bv + b;
            A *= a;
        }
        g_cA[tid * NCH + c] = A;    // channel-major for phase2
        g_cB[tid * NCH + c] = Bv;
    }
}

// =====================================================================
// Phase 2: hierarchical exclusive scan over 4096 chunk compositions.
// 64 blocks (one per channel), 256 threads, 16 chunks per thread.
// =====================================================================
__global__ __launch_bounds__(256) void phase2_kernel() {
    __shared__ float cAs[NCH], cBs[NCH];
    __shared__ float SA[256], SB[256];
    const int ch  = blockIdx.x;
    const int tid = threadIdx.x;

    for (int i = tid; i < NCH / 4; i += 256) {
        ((float4*)cAs)[i] = ((const float4*)(g_cA + (size_t)ch * NCH))[i];
        ((float4*)cBs)[i] = ((const float4*)(g_cB + (size_t)ch * NCH))[i];
    }
    __syncthreads();

    const int base = tid * 16;
    float A = 1.0f, Bv = 0.0f;
#pragma unroll
    for (int j = 0; j < 16; j++) {
        float a = cAs[base + j], b = cBs[base + j];
        Bv = a * Bv + b;
        A *= a;
    }
    SA[tid] = A; SB[tid] = Bv;
    __syncthreads();

#pragma unroll
    for (int s = 1; s < 256; s <<= 1) {
        float ta = SA[tid], tb = SB[tid];
        float pa = 1.0f, pb = 0.0f;
        if (tid >= s) { pa = SA[tid - s]; pb = SB[tid - s]; }
        __syncthreads();
        if (tid >= s) { SA[tid] = ta * pa; SB[tid] = ta * pb + tb; }
        __syncthreads();
    }

    float PB = (tid > 0) ? SB[tid - 1] : 0.0f;
#pragma unroll
    for (int j = 0; j < 16; j++) {
        g_pB[(size_t)(base + j) * NMEM + ch] = PB;
        PB = cAs[base + j] * PB + cBs[base + j];
    }
}

// =====================================================================
// Phase 3 (R4-proven form): load a,b; parallel in-chunk scan -> Zs; GEMM2.
// 512 threads. Scan: (ch, q) threads, q in 0..7, 16 rows each.
// =====================================================================
#define ZPAD 65
__global__ __launch_bounds__(512) void phase3_kernel(
    const float* __restrict__ W2, const float* __restrict__ B2,
    float* __restrict__ out) {
    extern __shared__ float sm[];
    float* As  = sm;                         // 128*64
    float* Bs  = As + 128 * 64;              // 128*64
    float* Zs  = Bs + 128 * 64;              // 128*65
    float* W2s = Zs + 128 * ZPAD;            // 64*32
    __shared__ float QA[8 * NMEM], QB[8 * NMEM];
    __shared__ float pBs[NMEM];

    const int tid = threadIdx.x;
    const int c   = blockIdx.x;
    const size_t base = (size_t)c * CHUNK * NMEM;

    for (int i = tid; i < CHUNK * NMEM / 4; i += 512) {
        ((float4*)As)[i] = ((const float4*)(g_a + base))[i];
        ((float4*)Bs)[i] = ((const float4*)(g_b + base))[i];
    }
    for (int i = tid; i < 64 * 32 / 4; i += 512)
        ((float4*)W2s)[i] = ((const float4*)W2)[i];
    if (tid < NMEM) pBs[tid] = g_pB[(size_t)c * NMEM + tid];
    __syncthreads();

    // pass 1: compose 16-row sub-segments
    const int ch = tid & 63, q = tid >> 6;   // q in 0..7
    {
        float A = 1.0f, Bv = 0.0f;
#pragma unroll
        for (int t = 0; t < 16; t++) {
            int row = q * 16 + t;
            float a = As[row * NMEM + ch];
            float b = Bs[row * NMEM + ch];
            Bv = a * Bv + b;
            A *= a;
        }
        QA[q * NMEM + ch] = A;
        QB[q * NMEM + ch] = Bv;
    }
    __syncthreads();

    // pass 2: sub-segment starting value, then replay writing z
    {
        float u = pBs[ch];
#pragma unroll
        for (int j = 0; j < 7; j++)
            if (j < q) u = QA[j * NMEM + ch] * u + QB[j * NMEM + ch];
#pragma unroll
        for (int t = 0; t < 16; t++) {
            int row = q * 16 + t;
            Zs[row * ZPAD + ch] = u;
            u = As[row * NMEM + ch] * u + Bs[row * NMEM + ch];
        }
    }
    __syncthreads();

    // GEMM2: Zs[128][64] @ W2s[64][32]. Thread tile 2 rows x 4 cols.
    const int colg = (tid & 7) * 4;    // 0..28
    const int rowg = (tid >> 3) * 2;   // 0..126
    float acc[2][4];
#pragma unroll
    for (int i = 0; i < 2; i++)
#pragma unroll
        for (int j = 0; j < 4; j++) acc[i][j] = 0.0f;

#pragma unroll 8
    for (int k = 0; k < 64; k++) {
        float4 w = *(const float4*)&W2s[k * 32 + colg];
        float z0 = Zs[(rowg + 0) * ZPAD + k];
        float z1 = Zs[(rowg + 1) * ZPAD + k];
        acc[0][0] += z0 * w.x; acc[0][1] += z0 * w.y; acc[0][2] += z0 * w.z; acc[0][3] += z0 * w.w;
        acc[1][0] += z1 * w.x; acc[1][1] += z1 * w.y; acc[1][2] += z1 * w.z; acc[1][3] += z1 * w.w;
    }

    float b0 = B2[colg + 0], b1 = B2[colg + 1], b2 = B2[colg + 2], b3 = B2[colg + 3];
#pragma unroll
    for (int i = 0; i < 2; i++) {
        float4 o;
        o.x = acc[i][0] + b0;
        o.y = acc[i][1] + b1;
        o.z = acc[i][2] + b2;
        o.w = acc[i][3] + b3;
        size_t row = (size_t)c * CHUNK + rowg + i;
        *(float4*)&out[row * OUTLEN + colg] = o;
    }
}

// =====================================================================
extern "C" void kernel_launch(void* const* d_in, const int* in_sizes, int n_in,
                              void* d_out, int out_size) {
    const float* x  = (const float*)d_in[0];   // [T, 64]
    const float* W1 = (const float*)d_in[1];   // [64, 128]
    const float* B1 = (const float*)d_in[2];   // [1, 128]
    const float* W2 = (const float*)d_in[3];   // [64, 32]
    const float* B2 = (const float*)d_in[4];   // [1, 32]
    float* out = (float*)d_out;                // [T, 32]

    const int P3_SMEM = (2 * 128 * 64 + 128 * ZPAD + 64 * 32) * 4;   // 107008

    cudaFuncSetAttribute(phase1_kernel, cudaFuncAttributeMaxDynamicSharedMemorySize, P1_DSMEM);
    cudaFuncSetAttribute(phase3_kernel, cudaFuncAttributeMaxDynamicSharedMemorySize, P3_SMEM);

    phase1_kernel<<<NCH, 512, P1_DSMEM>>>(x, W1, B1);
    phase2_kernel<<<64, 256>>>();
    phase3_kernel<<<NCH, 512, P3_SMEM>>>(W2, B2, out);
}

// round 9
// speedup vs baseline: 2.3288x; 1.1165x over previous
#include <cuda_runtime.h>
#include <cuda_bf16.h>
#include <cstdint>

// Problem constants
#define TT      524288
#define INLEN   64
#define NMEM    64
#define HID     128       // 2*NMEM
#define OUTLEN  32
#define CHUNK   64
#define NCH     (TT / CHUNK)   // 8192

// Scratch (device globals — allocation-free rule)
__device__ float g_a[TT * NMEM];        // 134 MB
__device__ float g_b[TT * NMEM];        // 134 MB
__device__ float g_cA[NMEM * NCH];      // per-chunk composed A, CHANNEL-MAJOR [ch][c]
__device__ float g_cB[NMEM * NCH];      // per-chunk composed B, CHANNEL-MAJOR [ch][c]
__device__ float g_pB[NCH * NMEM];      // exclusive-prefix B = z at chunk start [c][ch]
__device__ __align__(16) uint8_t g_W1t[36864];  // W1^T bf16 tiles: hi[128][72] then lo

// ===================== helpers =====================
__device__ __forceinline__ uint32_t smem_u32(const void* p) {
    uint32_t a;
    asm("{ .reg .u64 t; cvta.to.shared.u64 t, %1; cvt.u32.u64 %0, t; }" : "=r"(a) : "l"(p));
    return a;
}
__device__ __forceinline__ float sigmoidf_(float x) {
    return __fdividef(1.0f, 1.0f + __expf(-x));
}
// base-target tensor path (valid on plain sm_103)
__device__ __forceinline__ void ldsm_x4(uint32_t* r, uint32_t a) {
    asm volatile("ldmatrix.sync.aligned.m8n8.x4.shared.b16 {%0,%1,%2,%3}, [%4];"
                 : "=r"(r[0]), "=r"(r[1]), "=r"(r[2]), "=r"(r[3]) : "r"(a));
}
__device__ __forceinline__ void mma16816(float* c, const uint32_t* a,
                                         uint32_t b0, uint32_t b1) {
    asm volatile("mma.sync.aligned.m16n8k16.row.col.f32.bf16.bf16.f32 "
                 "{%0,%1,%2,%3}, {%4,%5,%6,%7}, {%8,%9}, {%0,%1,%2,%3};"
                 : "+f"(c[0]), "+f"(c[1]), "+f"(c[2]), "+f"(c[3])
                 : "r"(a[0]), "r"(a[1]), "r"(a[2]), "r"(a[3]), "r"(b0), "r"(b1));
}
// bf16 hi/lo split of two floats, packed as bf16x2 words
__device__ __forceinline__ void bfsplit2(float x, float y, uint32_t& hi, uint32_t& lo) {
    __nv_bfloat16 hx = __float2bfloat16_rn(x);
    __nv_bfloat16 hy = __float2bfloat16_rn(y);
    __nv_bfloat16 lx = __float2bfloat16_rn(x - __bfloat162float(hx));
    __nv_bfloat16 ly = __float2bfloat16_rn(y - __bfloat162float(hy));
    hi = (uint32_t)__bfloat16_as_ushort(hx) | ((uint32_t)__bfloat16_as_ushort(hy) << 16);
    lo = (uint32_t)__bfloat16_as_ushort(lx) | ((uint32_t)__bfloat16_as_ushort(ly) << 16);
}

// SMEM layout (byte offsets from 1024-aligned base). Tile rows padded to
// 72 bf16 = 144 B so ldmatrix row addresses hit distinct banks.
#define TSTRIDE 144
#define OFF_AH  0            // x hi  [64 m][72 k] bf16 : 9216 B
#define OFF_AL  9216         // x lo
#define OFF_BH  18432        // W1^T hi [128 n][72 k] bf16 : 18432 B
#define OFF_BL  36864        //           ... ends at 55296
#define OFF_HS  0            // f32 [64][132] = 33792 B, OVERLAYS tiles (post-MMA)
#define HS_ST   132
#define P1_DSMEM (55296 + 1024)

// =====================================================================
// Pre-kernel: convert W1 -> bf16 hi/lo tile image (exact smem layout).
// =====================================================================
__global__ __launch_bounds__(512) void convW1_kernel(const float* __restrict__ W1) {
    const int tid = threadIdx.x;
#pragma unroll
    for (int it = 0; it < 16; it++) {
        int i = it * 512 + tid;          // k = i>>7, n = i&127 (coalesced read)
        int k = i >> 7, n = i & 127;
        float v = W1[i];
        __nv_bfloat16 h = __float2bfloat16_rn(v);
        __nv_bfloat16 l = __float2bfloat16_rn(v - __bfloat162float(h));
        uint32_t off = n * TSTRIDE + k * 2;
        *(__nv_bfloat16*)(g_W1t + off)         = h;
        *(__nv_bfloat16*)(g_W1t + 18432 + off) = l;
    }
}

// =====================================================================
// GEMM1 via mma.sync bf16-split: 64-row chunk, 256 threads = 8 warps,
// warp = (m-tile 0..3, n-half 0..1). Writes Hs = sigmoid(x@W1+B1).
// =====================================================================
__device__ __forceinline__ void gemm1_hs(
    const float* __restrict__ xblk, const float* __restrict__ B1,
    char* base_c, uint32_t base_u, float* b1s, int tid) {

    char* Ah = base_c + OFF_AH;
    char* Al = base_c + OFF_AL;

    // ---- A tiles: x chunk [64 m][64 k] f32 -> bf16 hi/lo ----
#pragma unroll
    for (int it = 0; it < 4; it++) {
        int i = it * 256 + tid;          // float4 idx: row = i>>4, kq = i&15
        int row = i >> 4, kq = i & 15;
        float4 v = ((const float4*)xblk)[i];
        uint2 ph, pl;
        bfsplit2(v.x, v.y, ph.x, pl.x);
        bfsplit2(v.z, v.w, ph.y, pl.y);
        uint32_t off = row * TSTRIDE + kq * 8;
        *(uint2*)(Ah + off) = ph;
        *(uint2*)(Al + off) = pl;
    }
    // ---- B tiles: straight copy of pre-converted image (L2-hot) ----
#pragma unroll
    for (int it = 0; it < 9; it++) {
        int i = it * 256 + tid;          // 2304 uint4 = 36864 B
        ((uint4*)(base_c + OFF_BH))[i] = ((const uint4*)g_W1t)[i];
    }
    if (tid < HID) b1s[tid] = B1[tid];
    __syncthreads();

    const int wid  = tid >> 5, lane = tid & 31;
    const int mw   = wid & 3;      // m-tile: rows 16*mw..+15
    const int nh   = wid >> 2;     // n-half: n-tiles 8*nh..+7

    // ---- preload A fragments for 4 k-steps, hi+lo ----
    uint32_t AhF[4][4], AlF[4][4];
    {
        uint32_t arow  = mw * 16 + (lane & 15);
        uint32_t acol8 = (lane >> 4) << 3;     // 0 or 8
#pragma unroll
        for (int kk = 0; kk < 4; kk++) {
            uint32_t ad = base_u + OFF_AH + arow * TSTRIDE + (kk * 16 + acol8) * 2;
            ldsm_x4(AhF[kk], ad);
            ldsm_x4(AlF[kk], ad + (OFF_AL - OFF_AH));
        }
    }

    float acc[8][4];
#pragma unroll
    for (int j = 0; j < 8; j++)
#pragma unroll
        for (int q = 0; q < 4; q++) acc[j][q] = 0.0f;

    const uint32_t brow7 = lane & 7;
    const uint32_t bcol8 = (lane >> 3) << 3;   // 0,8,16,24 -> k offsets in 32-block
#pragma unroll
    for (int j = 0; j < 8; j++) {
        int jn = nh * 8 + j;                   // global n-tile
#pragma unroll
        for (int kk2 = 0; kk2 < 2; kk2++) {    // k 0-31, 32-63
            uint32_t bd = base_u + OFF_BH + (8 * jn + brow7) * TSTRIDE
                        + (kk2 * 32 + bcol8) * 2;
            uint32_t Bhf[4], Blf[4];
            ldsm_x4(Bhf, bd);
            ldsm_x4(Blf, bd + (OFF_BL - OFF_BH));
#pragma unroll
            for (int sh = 0; sh < 2; sh++) {
                int s = kk2 * 2 + sh;
                mma16816(acc[j], AhF[s], Bhf[sh * 2], Bhf[sh * 2 + 1]);  // xh*Wh
                mma16816(acc[j], AhF[s], Blf[sh * 2], Blf[sh * 2 + 1]);  // xh*Wl
                mma16816(acc[j], AlF[s], Bhf[sh * 2], Bhf[sh * 2 + 1]);  // xl*Wh
            }
        }
    }
    __syncthreads();   // all MMAs done -> bf16 tiles dead, Hs overlay safe

    // ---- epilogue: bias + sigmoid -> Hs ----
    float* Hs = (float*)(base_c + OFF_HS);
    {
        int r0 = mw * 16 + (lane >> 2);
        int c0 = (lane & 3) * 2;
#pragma unroll
        for (int j = 0; j < 8; j++) {
            int n = 8 * (nh * 8 + j) + c0;
            Hs[r0 * HS_ST + n]           = sigmoidf_(acc[j][0] + b1s[n]);
            Hs[r0 * HS_ST + n + 1]       = sigmoidf_(acc[j][1] + b1s[n + 1]);
            Hs[(r0 + 8) * HS_ST + n]     = sigmoidf_(acc[j][2] + b1s[n]);
            Hs[(r0 + 8) * HS_ST + n + 1] = sigmoidf_(acc[j][3] + b1s[n + 1]);
        }
    }
    __syncthreads();
}

// =====================================================================
// Phase 1: tensor GEMM1 -> Hs; write a,b to gmem; chunk aggregates.
// 256 threads, 2 CTAs/SM.
// =====================================================================
__global__ __launch_bounds__(256, 2) void phase1_kernel(
    const float* __restrict__ x, const float* __restrict__ B1) {
    extern __shared__ char dyn[];
    __shared__ float b1s[HID];
    __shared__ float QA[4 * NMEM], QB[4 * NMEM];

    const int tid = threadIdx.x;
    const int c   = blockIdx.x;
    uint32_t du = smem_u32(dyn);
    uint32_t bu = (du + 1023u) & ~1023u;
    char* base_c = dyn + (bu - du);
    float* Hs = (float*)(base_c + OFF_HS);

    gemm1_hs(x + (size_t)c * CHUNK * INLEN, B1, base_c, bu, b1s, tid);

    // write a,b to gmem (coalesced): layout [T][64]
    const size_t gbase = (size_t)c * CHUNK * NMEM;
#pragma unroll 4
    for (int i = tid; i < CHUNK * NMEM; i += 256) {
        int t = i >> 6, ch = i & 63;
        float l = Hs[t * HS_ST + ch];
        float r = Hs[t * HS_ST + ch + 64];
        g_a[gbase + i] = l * r;
        g_b[gbase + i] = 1.0f - l;
    }

    // compose: 4 segments of 16 rows per channel (exactly 256 threads)
    const int ch = tid & 63, q = tid >> 6;
    {
        float A = 1.0f, Bv = 0.0f;
#pragma unroll
        for (int t = 0; t < 16; t++) {
            int row = q * 16 + t;
            float l = Hs[row * HS_ST + ch];
            float r = Hs[row * HS_ST + ch + 64];
            float a = l * r, b = 1.0f - l;
            Bv = a * Bv + b;
            A *= a;
        }
        QA[q * NMEM + ch] = A;
        QB[q * NMEM + ch] = Bv;
    }
    __syncthreads();
    if (tid < NMEM) {
        float A = 1.0f, Bv = 0.0f;
#pragma unroll
        for (int qq = 0; qq < 4; qq++) {
            float a = QA[qq * NMEM + tid], b = QB[qq * NMEM + tid];
            Bv = a * Bv + b;
            A *= a;
        }
        g_cA[tid * NCH + c] = A;    // channel-major for phase2
        g_cB[tid * NCH + c] = Bv;
    }
}

// =====================================================================
// Phase 2: hierarchical exclusive scan over 8192 chunk compositions.
// 64 blocks (one per channel), 256 threads, 32 chunks per thread.
// =====================================================================
#define P2_DSMEM (2 * NCH * 4)
__global__ __launch_bounds__(256) void phase2_kernel() {
    extern __shared__ float p2sm[];
    float* cAs = p2sm;           // [8192]
    float* cBs = p2sm + NCH;     // [8192]
    __shared__ float SA[256], SB[256];
    const int ch  = blockIdx.x;
    const int tid = threadIdx.x;

    for (int i = tid; i < NCH / 4; i += 256) {
        ((float4*)cAs)[i] = ((const float4*)(g_cA + (size_t)ch * NCH))[i];
        ((float4*)cBs)[i] = ((const float4*)(g_cB + (size_t)ch * NCH))[i];
    }
    __syncthreads();

    const int base = tid * 32;
    float A = 1.0f, Bv = 0.0f;
#pragma unroll
    for (int j = 0; j < 32; j++) {
        float a = cAs[base + j], b = cBs[base + j];
        Bv = a * Bv + b;
        A *= a;
    }
    SA[tid] = A; SB[tid] = Bv;
    __syncthreads();

#pragma unroll
    for (int s = 1; s < 256; s <<= 1) {
        float ta = SA[tid], tb = SB[tid];
        float pa = 1.0f, pb = 0.0f;
        if (tid >= s) { pa = SA[tid - s]; pb = SB[tid - s]; }
        __syncthreads();
        if (tid >= s) { SA[tid] = ta * pa; SB[tid] = ta * pb + tb; }
        __syncthreads();
    }

    float PB = (tid > 0) ? SB[tid - 1] : 0.0f;
#pragma unroll
    for (int j = 0; j < 32; j++) {
        g_pB[(size_t)(base + j) * NMEM + ch] = PB;
        PB = cAs[base + j] * PB + cBs[base + j];
    }
}

// =====================================================================
// Phase 3: a,b in REGISTERS (no As/Bs smem); scan -> Zs; GEMM2.
// 256 threads: thread = (ch 0..63, q 0..3), 16 rows each.
// =====================================================================
#define ZPAD 65
__global__ __launch_bounds__(256) void phase3_kernel(
    const float* __restrict__ W2, const float* __restrict__ B2,
    float* __restrict__ out) {
    __shared__ float Zs[CHUNK * ZPAD];       // 64*65
    __shared__ float W2s[64 * 32];
    __shared__ float QA[4 * NMEM], QB[4 * NMEM];
    __shared__ float pBs[NMEM];

    const int tid = threadIdx.x;
    const int c   = blockIdx.x;
    const size_t base = (size_t)c * CHUNK * NMEM;

    for (int i = tid; i < 64 * 32 / 4; i += 256)
        ((float4*)W2s)[i] = ((const float4*)W2)[i];
    if (tid < NMEM) pBs[tid] = g_pB[(size_t)c * NMEM + tid];

    // load a,b for this thread's 16 rows into registers (coalesced)
    const int ch = tid & 63, q = tid >> 6;
    float ar[16], br[16];
#pragma unroll
    for (int t = 0; t < 16; t++) {
        int row = q * 16 + t;
        ar[t] = g_a[base + row * NMEM + ch];
        br[t] = g_b[base + row * NMEM + ch];
    }

    // pass 1: compose in registers
    {
        float A = 1.0f, Bv = 0.0f;
#pragma unroll
        for (int t = 0; t < 16; t++) {
            Bv = ar[t] * Bv + br[t];
            A *= ar[t];
        }
        QA[q * NMEM + ch] = A;
        QB[q * NMEM + ch] = Bv;
    }
    __syncthreads();

    // pass 2: starting value, replay from registers writing Zs
    {
        float u = pBs[ch];
#pragma unroll
        for (int j = 0; j < 3; j++)
            if (j < q) u = QA[j * NMEM + ch] * u + QB[j * NMEM + ch];
#pragma unroll
        for (int t = 0; t < 16; t++) {
            int row = q * 16 + t;
            Zs[row * ZPAD + ch] = u;
            u = ar[t] * u + br[t];
        }
    }
    __syncthreads();

    // GEMM2: Zs[64][64] @ W2s[64][32]. Thread tile 2 rows x 4 cols.
    const int colg = (tid & 7) * 4;    // 0..28
    const int rowg = (tid >> 3) * 2;   // 0..62
    float acc[2][4];
#pragma unroll
    for (int i = 0; i < 2; i++)
#pragma unroll
        for (int j = 0; j < 4; j++) acc[i][j] = 0.0f;

#pragma unroll 8
    for (int k = 0; k < 64; k++) {
        float4 w = *(const float4*)&W2s[k * 32 + colg];
        float z0 = Zs[(rowg + 0) * ZPAD + k];
        float z1 = Zs[(rowg + 1) * ZPAD + k];
        acc[0][0] += z0 * w.x; acc[0][1] += z0 * w.y; acc[0][2] += z0 * w.z; acc[0][3] += z0 * w.w;
        acc[1][0] += z1 * w.x; acc[1][1] += z1 * w.y; acc[1][2] += z1 * w.z; acc[1][3] += z1 * w.w;
    }

    float b0 = B2[colg + 0], b1 = B2[colg + 1], b2 = B2[colg + 2], b3 = B2[colg + 3];
#pragma unroll
    for (int i = 0; i < 2; i++) {
        float4 o;
        o.x = acc[i][0] + b0;
        o.y = acc[i][1] + b1;
        o.z = acc[i][2] + b2;
        o.w = acc[i][3] + b3;
        size_t row = (size_t)c * CHUNK + rowg + i;
        *(float4*)&out[row * OUTLEN + colg] = o;
    }
}

// =====================================================================
extern "C" void kernel_launch(void* const* d_in, const int* in_sizes, int n_in,
                              void* d_out, int out_size) {
    const float* x  = (const float*)d_in[0];   // [T, 64]
    const float* W1 = (const float*)d_in[1];   // [64, 128]
    const float* B1 = (const float*)d_in[2];   // [1, 128]
    const float* W2 = (const float*)d_in[3];   // [64, 32]
    const float* B2 = (const float*)d_in[4];   // [1, 32]
    float* out = (float*)d_out;                // [T, 32]

    cudaFuncSetAttribute(phase1_kernel, cudaFuncAttributeMaxDynamicSharedMemorySize, P1_DSMEM);
    cudaFuncSetAttribute(phase2_kernel, cudaFuncAttributeMaxDynamicSharedMemorySize, P2_DSMEM);

    convW1_kernel<<<1, 512>>>(W1);
    phase1_kernel<<<NCH, 256, P1_DSMEM>>>(x, B1);
    phase2_kernel<<<64, 256, P2_DSMEM>>>();
    phase3_kernel<<<NCH, 256>>>(W2, B2, out);
}